// round 14
// baseline (speedup 1.0000x reference)
#include <cuda_runtime.h>

// Problem constants (B=2, S=2048, D=1024, H=16, hd=64)
#define D_MODEL 1024
#define SEQ     2048
#define NHEADS  16
#define HDIM    64
#define BATCH   2
#define MROWS   4096   // B * S

// Scratch (device globals: allocation-free per harness rules)
__device__ float g_Q[(size_t)MROWS * D_MODEL];
__device__ float g_K[(size_t)MROWS * D_MODEL];
__device__ float g_V[(size_t)MROWS * D_MODEL];
__device__ float g_A[(size_t)MROWS * D_MODEL];

// ---------------------------------------------------------------------------
// SGEMM: C[M,N] = A[M,K] @ B[K,N]   (row-major, fp32)
// 128x128 block tile, BK=8, 256 threads, 8x8 register tile per thread.
// ---------------------------------------------------------------------------
__global__ __launch_bounds__(256, 2)
void sgemm128(const float* __restrict__ A, const float* __restrict__ B,
              float* __restrict__ C, int M, int N, int K)
{
    __shared__ float As[8][128];   // transposed A tile: As[k][m]
    __shared__ float Bs[8][128];   // natural B tile:    Bs[k][n]

    const int tid = threadIdx.x;
    const int tx  = tid & 15;      // 0..15 -> output cols
    const int ty  = tid >> 4;      // 0..15 -> output rows
    const int bm  = blockIdx.y * 128;
    const int bn  = blockIdx.x * 128;

    const int arow = tid >> 1;         // 0..127
    const int acol = (tid & 1) * 4;    // 0 or 4
    const int brow = tid >> 5;         // 0..7
    const int bcol = (tid & 31) * 4;   // 0..124

    const float* Aptr = A + (size_t)(bm + arow) * K + acol;
    const float* Bptr = B + (size_t)brow * N + (bn + bcol);

    float acc[8][8];
    #pragma unroll
    for (int i = 0; i < 8; i++)
        #pragma unroll
        for (int j = 0; j < 8; j++) acc[i][j] = 0.f;

    for (int k0 = 0; k0 < K; k0 += 8) {
        float4 a4 = *(const float4*)Aptr;   // prefetch before barrier
        float4 b4 = *(const float4*)Bptr;
        __syncthreads();                    // previous tile's compute done
        As[acol + 0][arow] = a4.x;
        As[acol + 1][arow] = a4.y;
        As[acol + 2][arow] = a4.z;
        As[acol + 3][arow] = a4.w;
        *(float4*)&Bs[brow][bcol] = b4;
        __syncthreads();
        Aptr += 8;
        Bptr += (size_t)8 * N;

        #pragma unroll
        for (int k = 0; k < 8; k++) {
            float a[8], b[8];
            *(float4*)&a[0] = *(const float4*)&As[k][ty * 4];
            *(float4*)&a[4] = *(const float4*)&As[k][64 + ty * 4];
            *(float4*)&b[0] = *(const float4*)&Bs[k][tx * 4];
            *(float4*)&b[4] = *(const float4*)&Bs[k][64 + tx * 4];
            #pragma unroll
            for (int i = 0; i < 8; i++)
                #pragma unroll
                for (int j = 0; j < 8; j++)
                    acc[i][j] += a[i] * b[j];
        }
    }

    #pragma unroll
    for (int i = 0; i < 8; i++) {
        int lrow = (i < 4) ? (ty * 4 + i) : (64 + ty * 4 + (i - 4));
        float* Crow = C + (size_t)(bm + lrow) * N + bn;
        float4 c0 = make_float4(acc[i][0], acc[i][1], acc[i][2], acc[i][3]);
        float4 c1 = make_float4(acc[i][4], acc[i][5], acc[i][6], acc[i][7]);
        *(float4*)&Crow[tx * 4]      = c0;
        *(float4*)&Crow[64 + tx * 4] = c1;
    }
}

// ---------------------------------------------------------------------------
// Flash-attention with ALiBi bias (non-causal, |i-j| distance bias).
// One CTA = (batch b, head h, 64 query rows). 256 threads.
// S/P GEMMs: 4x4 register micro-tile per thread; online softmax with
// 16-lane shfl_xor reductions (16 threads own each query row).
// smem: Qs (Q^T), Ks (K^T, reused as P^T), Vs — each 64 x 68 floats.
// ---------------------------------------------------------------------------
#define PAD 68
#define FLASH_SMEM (3 * 64 * PAD * (int)sizeof(float))   // 52224 B

__global__ __launch_bounds__(256, 2)
void flash_alibi(const float* __restrict__ Q, const float* __restrict__ K,
                 const float* __restrict__ V, float* __restrict__ O)
{
    extern __shared__ float sm[];
    float* Qs = sm;                 // [d][r] : Qs[d*PAD + r]
    float* Ks = sm + 64 * PAD;      // [d][k] ; later reused as Ps[k][r]
    float* Vs = sm + 2 * 64 * PAD;  // [k][d] : Vs[k*PAD + d]

    const int tid = threadIdx.x;
    const int tx  = tid & 15;       // key/dim micro-tile index
    const int ty  = tid >> 4;       // query-row micro-tile index
    const int bh  = blockIdx.y;
    const int b   = bh >> 4;
    const int h   = bh & 15;
    const int q0  = blockIdx.x * 64;

    // slopes[h] = (2^-0.5)^(h+1)
    const float slope = exp2f(-0.5f * (float)(h + 1));

    const float* Qb = Q + ((size_t)b * SEQ) * D_MODEL + h * HDIM;
    const float* Kb = K + ((size_t)b * SEQ) * D_MODEL + h * HDIM;
    const float* Vb = V + ((size_t)b * SEQ) * D_MODEL + h * HDIM;

    // Load Q tile (transposed) once
    #pragma unroll
    for (int i = 0; i < 16; i++) {
        int idx = tid + i * 256;
        int r = idx >> 6, d = idx & 63;
        Qs[d * PAD + r] = Qb[(size_t)(q0 + r) * D_MODEL + d];
    }

    float mrow[4], lrow[4], acc[4][4];
    #pragma unroll
    for (int i = 0; i < 4; i++) {
        mrow[i] = -1e30f; lrow[i] = 0.f;
        #pragma unroll
        for (int j = 0; j < 4; j++) acc[i][j] = 0.f;
    }

    for (int kt = 0; kt < SEQ; kt += 64) {
        __syncthreads();   // previous PV reads of Ks(=Ps)/Vs are done
        #pragma unroll
        for (int i = 0; i < 16; i++) {
            int idx = tid + i * 256;
            int r = idx >> 6, d = idx & 63;
            Ks[d * PAD + r] = Kb[(size_t)(kt + r) * D_MODEL + d];
            Vs[r * PAD + d] = Vb[(size_t)(kt + r) * D_MODEL + d];
        }
        __syncthreads();

        // S = Q @ K^T  (4x4 per thread over d)
        float s[4][4];
        #pragma unroll
        for (int i = 0; i < 4; i++)
            #pragma unroll
            for (int j = 0; j < 4; j++) s[i][j] = 0.f;

        #pragma unroll 8
        for (int d = 0; d < 64; d++) {
            float4 q4 = *(const float4*)&Qs[d * PAD + ty * 4];
            float4 k4 = *(const float4*)&Ks[d * PAD + tx * 4];
            float qa[4] = {q4.x, q4.y, q4.z, q4.w};
            float ka[4] = {k4.x, k4.y, k4.z, k4.w};
            #pragma unroll
            for (int i = 0; i < 4; i++)
                #pragma unroll
                for (int j = 0; j < 4; j++)
                    s[i][j] += qa[i] * ka[j];
        }

        // scale + ALiBi bias
        #pragma unroll
        for (int i = 0; i < 4; i++) {
            float qpos = (float)(q0 + ty * 4 + i);
            #pragma unroll
            for (int j = 0; j < 4; j++) {
                float kpos = (float)(kt + tx * 4 + j);
                s[i][j] = s[i][j] * 0.125f - slope * fabsf(qpos - kpos);
            }
        }

        // online softmax (16 threads per row: lanes (ty&1)*16 + tx)
        #pragma unroll
        for (int i = 0; i < 4; i++) {
            float mt = fmaxf(fmaxf(s[i][0], s[i][1]), fmaxf(s[i][2], s[i][3]));
            #pragma unroll
            for (int o = 1; o < 16; o <<= 1)
                mt = fmaxf(mt, __shfl_xor_sync(0xffffffffu, mt, o));
            float mnew = fmaxf(mrow[i], mt);
            float corr = __expf(mrow[i] - mnew);   // exp(-1e30)=0 first time
            float lt = 0.f;
            #pragma unroll
            for (int j = 0; j < 4; j++) {
                float p = __expf(s[i][j] - mnew);
                s[i][j] = p;
                lt += p;
            }
            #pragma unroll
            for (int o = 1; o < 16; o <<= 1)
                lt += __shfl_xor_sync(0xffffffffu, lt, o);
            lrow[i] = lrow[i] * corr + lt;
            mrow[i] = mnew;
            #pragma unroll
            for (int j = 0; j < 4; j++) acc[i][j] *= corr;
        }

        __syncthreads();   // all S-GEMM reads of Ks done before P overwrite
        #pragma unroll
        for (int j = 0; j < 4; j++)
            #pragma unroll
            for (int i = 0; i < 4; i++)
                Ks[(tx * 4 + j) * PAD + (ty * 4 + i)] = s[i][j];  // Ps[k][r]
        __syncthreads();

        // O += P @ V   (4x4 per thread over k)
        #pragma unroll 8
        for (int k = 0; k < 64; k++) {
            float4 p4 = *(const float4*)&Ks[k * PAD + ty * 4];
            float4 v4 = *(const float4*)&Vs[k * PAD + tx * 4];
            float pa[4] = {p4.x, p4.y, p4.z, p4.w};
            float va[4] = {v4.x, v4.y, v4.z, v4.w};
            #pragma unroll
            for (int i = 0; i < 4; i++)
                #pragma unroll
                for (int j = 0; j < 4; j++)
                    acc[i][j] += pa[i] * va[j];
        }
    }

    // normalize + store
    float* Ob = O + ((size_t)b * SEQ + q0) * D_MODEL + h * HDIM;
    #pragma unroll
    for (int i = 0; i < 4; i++) {
        float inv = 1.f / lrow[i];
        float4 o4 = make_float4(acc[i][0] * inv, acc[i][1] * inv,
                                acc[i][2] * inv, acc[i][3] * inv);
        *(float4*)&Ob[(size_t)(ty * 4 + i) * D_MODEL + tx * 4] = o4;
    }
}

// ---------------------------------------------------------------------------
// kernel_launch: Q/K/V projections -> flash attention -> output projection.
// All launches stream-ordered; graph-capturable; allocation-free.
// ---------------------------------------------------------------------------
extern "C" void kernel_launch(void* const* d_in, const int* in_sizes, int n_in,
                              void* d_out, int out_size)
{
    const float* q  = (const float*)d_in[0];
    const float* k  = (const float*)d_in[1];
    const float* v  = (const float*)d_in[2];
    const float* Wq = (const float*)d_in[3];
    const float* Wk = (const float*)d_in[4];
    const float* Wv = (const float*)d_in[5];
    const float* Wo = (const float*)d_in[6];
    float* out = (float*)d_out;

    float *pQ, *pK, *pV, *pA;
    cudaGetSymbolAddress((void**)&pQ, g_Q);
    cudaGetSymbolAddress((void**)&pK, g_K);
    cudaGetSymbolAddress((void**)&pV, g_V);
    cudaGetSymbolAddress((void**)&pA, g_A);

    cudaFuncSetAttribute(flash_alibi,
                         cudaFuncAttributeMaxDynamicSharedMemorySize,
                         FLASH_SMEM);

    dim3 gg(D_MODEL / 128, MROWS / 128);   // (8, 32)

    sgemm128<<<gg, 256>>>(q, Wq, pQ, MROWS, D_MODEL, D_MODEL);
    sgemm128<<<gg, 256>>>(k, Wk, pK, MROWS, D_MODEL, D_MODEL);
    sgemm128<<<gg, 256>>>(v, Wv, pV, MROWS, D_MODEL, D_MODEL);

    dim3 fg(SEQ / 64, BATCH * NHEADS);     // (32, 32)
    flash_alibi<<<fg, 256, FLASH_SMEM>>>(pQ, pK, pV, pA);

    sgemm128<<<gg, 256>>>(pA, Wo, out, MROWS, D_MODEL, D_MODEL);
}

// round 15
// speedup vs baseline: 1.0011x; 1.0011x over previous
#include <cuda_runtime.h>

// Problem constants (B=2, S=2048, D=1024, H=16, hd=64)
#define D_MODEL 1024
#define SEQ     2048
#define NHEADS  16
#define HDIM    64
#define BATCH   2
#define MROWS   4096   // B * S

// Scratch (device globals: allocation-free per harness rules)
__device__ float g_Q[(size_t)MROWS * D_MODEL];
__device__ float g_K[(size_t)MROWS * D_MODEL];
__device__ float g_V[(size_t)MROWS * D_MODEL];
__device__ float g_A[(size_t)MROWS * D_MODEL];

// ---------------------------------------------------------------------------
// SGEMM: C[M,N] = A[M,K] @ B[K,N]   (row-major, fp32)
// 128x128 block tile, BK=8, 256 threads, 8x8 register tile per thread.
// ---------------------------------------------------------------------------
__global__ __launch_bounds__(256, 2)
void sgemm128(const float* __restrict__ A, const float* __restrict__ B,
              float* __restrict__ C, int M, int N, int K)
{
    __shared__ float As[8][128];   // transposed A tile: As[k][m]
    __shared__ float Bs[8][128];   // natural B tile:    Bs[k][n]

    const int tid = threadIdx.x;
    const int tx  = tid & 15;      // 0..15 -> output cols
    const int ty  = tid >> 4;      // 0..15 -> output rows
    const int bm  = blockIdx.y * 128;
    const int bn  = blockIdx.x * 128;

    const int arow = tid >> 1;         // 0..127
    const int acol = (tid & 1) * 4;    // 0 or 4
    const int brow = tid >> 5;         // 0..7
    const int bcol = (tid & 31) * 4;   // 0..124

    const float* Aptr = A + (size_t)(bm + arow) * K + acol;
    const float* Bptr = B + (size_t)brow * N + (bn + bcol);

    float acc[8][8];
    #pragma unroll
    for (int i = 0; i < 8; i++)
        #pragma unroll
        for (int j = 0; j < 8; j++) acc[i][j] = 0.f;

    for (int k0 = 0; k0 < K; k0 += 8) {
        float4 a4 = *(const float4*)Aptr;   // prefetch before barrier
        float4 b4 = *(const float4*)Bptr;
        __syncthreads();                    // previous tile's compute done
        As[acol + 0][arow] = a4.x;
        As[acol + 1][arow] = a4.y;
        As[acol + 2][arow] = a4.z;
        As[acol + 3][arow] = a4.w;
        *(float4*)&Bs[brow][bcol] = b4;
        __syncthreads();
        Aptr += 8;
        Bptr += (size_t)8 * N;

        #pragma unroll
        for (int k = 0; k < 8; k++) {
            float a[8], b[8];
            *(float4*)&a[0] = *(const float4*)&As[k][ty * 4];
            *(float4*)&a[4] = *(const float4*)&As[k][64 + ty * 4];
            *(float4*)&b[0] = *(const float4*)&Bs[k][tx * 4];
            *(float4*)&b[4] = *(const float4*)&Bs[k][64 + tx * 4];
            #pragma unroll
            for (int i = 0; i < 8; i++)
                #pragma unroll
                for (int j = 0; j < 8; j++)
                    acc[i][j] += a[i] * b[j];
        }
    }

    #pragma unroll
    for (int i = 0; i < 8; i++) {
        int lrow = (i < 4) ? (ty * 4 + i) : (64 + ty * 4 + (i - 4));
        float* Crow = C + (size_t)(bm + lrow) * N + bn;
        float4 c0 = make_float4(acc[i][0], acc[i][1], acc[i][2], acc[i][3]);
        float4 c1 = make_float4(acc[i][4], acc[i][5], acc[i][6], acc[i][7]);
        *(float4*)&Crow[tx * 4]      = c0;
        *(float4*)&Crow[64 + tx * 4] = c1;
    }
}

// ---------------------------------------------------------------------------
// Flash-attention with ALiBi bias (non-causal, |i-j| distance bias).
// One CTA = (batch b, head h, 64 query rows). 256 threads.
// S/P GEMMs: 4x4 register micro-tile per thread; online softmax with
// 16-lane shfl_xor reductions (16 threads own each query row).
// smem: Qs (Q^T), Ks (K^T, reused as P^T), Vs — each 64 x 68 floats.
// ---------------------------------------------------------------------------
#define PAD 68
#define FLASH_SMEM (3 * 64 * PAD * (int)sizeof(float))   // 52224 B

__global__ __launch_bounds__(256, 2)
void flash_alibi(const float* __restrict__ Q, const float* __restrict__ K,
                 const float* __restrict__ V, float* __restrict__ O)
{
    extern __shared__ float sm[];
    float* Qs = sm;                 // [d][r] : Qs[d*PAD + r]
    float* Ks = sm + 64 * PAD;      // [d][k] ; later reused as Ps[k][r]
    float* Vs = sm + 2 * 64 * PAD;  // [k][d] : Vs[k*PAD + d]

    const int tid = threadIdx.x;
    const int tx  = tid & 15;       // key/dim micro-tile index
    const int ty  = tid >> 4;       // query-row micro-tile index
    const int bh  = blockIdx.y;
    const int b   = bh >> 4;
    const int h   = bh & 15;
    const int q0  = blockIdx.x * 64;

    // slopes[h] = (2^-0.5)^(h+1)
    const float slope = exp2f(-0.5f * (float)(h + 1));

    const float* Qb = Q + ((size_t)b * SEQ) * D_MODEL + h * HDIM;
    const float* Kb = K + ((size_t)b * SEQ) * D_MODEL + h * HDIM;
    const float* Vb = V + ((size_t)b * SEQ) * D_MODEL + h * HDIM;

    // Load Q tile (transposed) once
    #pragma unroll
    for (int i = 0; i < 16; i++) {
        int idx = tid + i * 256;
        int r = idx >> 6, d = idx & 63;
        Qs[d * PAD + r] = Qb[(size_t)(q0 + r) * D_MODEL + d];
    }

    float mrow[4], lrow[4], acc[4][4];
    #pragma unroll
    for (int i = 0; i < 4; i++) {
        mrow[i] = -1e30f; lrow[i] = 0.f;
        #pragma unroll
        for (int j = 0; j < 4; j++) acc[i][j] = 0.f;
    }

    for (int kt = 0; kt < SEQ; kt += 64) {
        __syncthreads();   // previous PV reads of Ks(=Ps)/Vs are done
        #pragma unroll
        for (int i = 0; i < 16; i++) {
            int idx = tid + i * 256;
            int r = idx >> 6, d = idx & 63;
            Ks[d * PAD + r] = Kb[(size_t)(kt + r) * D_MODEL + d];
            Vs[r * PAD + d] = Vb[(size_t)(kt + r) * D_MODEL + d];
        }
        __syncthreads();

        // S = Q @ K^T  (4x4 per thread over d)
        float s[4][4];
        #pragma unroll
        for (int i = 0; i < 4; i++)
            #pragma unroll
            for (int j = 0; j < 4; j++) s[i][j] = 0.f;

        #pragma unroll 8
        for (int d = 0; d < 64; d++) {
            float4 q4 = *(const float4*)&Qs[d * PAD + ty * 4];
            float4 k4 = *(const float4*)&Ks[d * PAD + tx * 4];
            float qa[4] = {q4.x, q4.y, q4.z, q4.w};
            float ka[4] = {k4.x, k4.y, k4.z, k4.w};
            #pragma unroll
            for (int i = 0; i < 4; i++)
                #pragma unroll
                for (int j = 0; j < 4; j++)
                    s[i][j] += qa[i] * ka[j];
        }

        // scale + ALiBi bias
        #pragma unroll
        for (int i = 0; i < 4; i++) {
            float qpos = (float)(q0 + ty * 4 + i);
            #pragma unroll
            for (int j = 0; j < 4; j++) {
                float kpos = (float)(kt + tx * 4 + j);
                s[i][j] = s[i][j] * 0.125f - slope * fabsf(qpos - kpos);
            }
        }

        // online softmax (16 threads per row: lanes (ty&1)*16 + tx)
        #pragma unroll
        for (int i = 0; i < 4; i++) {
            float mt = fmaxf(fmaxf(s[i][0], s[i][1]), fmaxf(s[i][2], s[i][3]));
            #pragma unroll
            for (int o = 1; o < 16; o <<= 1)
                mt = fmaxf(mt, __shfl_xor_sync(0xffffffffu, mt, o));
            float mnew = fmaxf(mrow[i], mt);
            float corr = __expf(mrow[i] - mnew);   // exp(-1e30)=0 first time
            float lt = 0.f;
            #pragma unroll
            for (int j = 0; j < 4; j++) {
                float p = __expf(s[i][j] - mnew);
                s[i][j] = p;
                lt += p;
            }
            #pragma unroll
            for (int o = 1; o < 16; o <<= 1)
                lt += __shfl_xor_sync(0xffffffffu, lt, o);
            lrow[i] = lrow[i] * corr + lt;
            mrow[i] = mnew;
            #pragma unroll
            for (int j = 0; j < 4; j++) acc[i][j] *= corr;
        }

        __syncthreads();   // all S-GEMM reads of Ks done before P overwrite
        #pragma unroll
        for (int j = 0; j < 4; j++)
            #pragma unroll
            for (int i = 0; i < 4; i++)
                Ks[(tx * 4 + j) * PAD + (ty * 4 + i)] = s[i][j];  // Ps[k][r]
        __syncthreads();

        // O += P @ V   (4x4 per thread over k)
        #pragma unroll 8
        for (int k = 0; k < 64; k++) {
            float4 p4 = *(const float4*)&Ks[k * PAD + ty * 4];
            float4 v4 = *(const float4*)&Vs[k * PAD + tx * 4];
            float pa[4] = {p4.x, p4.y, p4.z, p4.w};
            float va[4] = {v4.x, v4.y, v4.z, v4.w};
            #pragma unroll
            for (int i = 0; i < 4; i++)
                #pragma unroll
                for (int j = 0; j < 4; j++)
                    acc[i][j] += pa[i] * va[j];
        }
    }

    // normalize + store
    float* Ob = O + ((size_t)b * SEQ + q0) * D_MODEL + h * HDIM;
    #pragma unroll
    for (int i = 0; i < 4; i++) {
        float inv = 1.f / lrow[i];
        float4 o4 = make_float4(acc[i][0] * inv, acc[i][1] * inv,
                                acc[i][2] * inv, acc[i][3] * inv);
        *(float4*)&Ob[(size_t)(ty * 4 + i) * D_MODEL + tx * 4] = o4;
    }
}

// ---------------------------------------------------------------------------
// kernel_launch: Q/K/V projections -> flash attention -> output projection.
// All launches stream-ordered; graph-capturable; allocation-free.
// ---------------------------------------------------------------------------
extern "C" void kernel_launch(void* const* d_in, const int* in_sizes, int n_in,
                              void* d_out, int out_size)
{
    const float* q  = (const float*)d_in[0];
    const float* k  = (const float*)d_in[1];
    const float* v  = (const float*)d_in[2];
    const float* Wq = (const float*)d_in[3];
    const float* Wk = (const float*)d_in[4];
    const float* Wv = (const float*)d_in[5];
    const float* Wo = (const float*)d_in[6];
    float* out = (float*)d_out;

    float *pQ, *pK, *pV, *pA;
    cudaGetSymbolAddress((void**)&pQ, g_Q);
    cudaGetSymbolAddress((void**)&pK, g_K);
    cudaGetSymbolAddress((void**)&pV, g_V);
    cudaGetSymbolAddress((void**)&pA, g_A);

    cudaFuncSetAttribute(flash_alibi,
                         cudaFuncAttributeMaxDynamicSharedMemorySize,
                         FLASH_SMEM);

    dim3 gg(D_MODEL / 128, MROWS / 128);   // (8, 32)

    sgemm128<<<gg, 256>>>(q, Wq, pQ, MROWS, D_MODEL, D_MODEL);
    sgemm128<<<gg, 256>>>(k, Wk, pK, MROWS, D_MODEL, D_MODEL);
    sgemm128<<<gg, 256>>>(v, Wv, pV, MROWS, D_MODEL, D_MODEL);

    dim3 fg(SEQ / 64, BATCH * NHEADS);     // (32, 32)
    flash_alibi<<<fg, 256, FLASH_SMEM>>>(pQ, pK, pV, pA);

    sgemm128<<<gg, 256>>>(pA, Wo, out, MROWS, D_MODEL, D_MODEL);
}

// round 16
// speedup vs baseline: 1.0410x; 1.0398x over previous
#include <cuda_runtime.h>

// Problem constants (B=2, S=2048, D=1024, H=16, hd=64)
#define D_MODEL 1024
#define SEQ     2048
#define NHEADS  16
#define HDIM    64
#define BATCH   2
#define MROWS   4096   // B * S

// Scratch (device globals: allocation-free per harness rules)
__device__ float g_Q[(size_t)MROWS * D_MODEL];
__device__ float g_K[(size_t)MROWS * D_MODEL];
__device__ float g_V[(size_t)MROWS * D_MODEL];
__device__ float g_A[(size_t)MROWS * D_MODEL];

// ---------------------------------------------------------------------------
// SGEMM: C[M,N] = A[M,K] @ B[K,N]   (row-major, fp32)
// 128x128 block tile, BK=8, 256 threads, 8x8 register tile per thread.
// ---------------------------------------------------------------------------
__global__ __launch_bounds__(256, 2)
void sgemm128(const float* __restrict__ A, const float* __restrict__ B,
              float* __restrict__ C, int M, int N, int K)
{
    __shared__ float As[8][128];   // transposed A tile: As[k][m]
    __shared__ float Bs[8][128];   // natural B tile:    Bs[k][n]

    const int tid = threadIdx.x;
    const int tx  = tid & 15;      // 0..15 -> output cols
    const int ty  = tid >> 4;      // 0..15 -> output rows
    const int bm  = blockIdx.y * 128;
    const int bn  = blockIdx.x * 128;

    const int arow = tid >> 1;         // 0..127
    const int acol = (tid & 1) * 4;    // 0 or 4
    const int brow = tid >> 5;         // 0..7
    const int bcol = (tid & 31) * 4;   // 0..124

    const float* Aptr = A + (size_t)(bm + arow) * K + acol;
    const float* Bptr = B + (size_t)brow * N + (bn + bcol);

    float acc[8][8];
    #pragma unroll
    for (int i = 0; i < 8; i++)
        #pragma unroll
        for (int j = 0; j < 8; j++) acc[i][j] = 0.f;

    for (int k0 = 0; k0 < K; k0 += 8) {
        float4 a4 = *(const float4*)Aptr;   // prefetch before barrier
        float4 b4 = *(const float4*)Bptr;
        __syncthreads();                    // previous tile's compute done
        As[acol + 0][arow] = a4.x;
        As[acol + 1][arow] = a4.y;
        As[acol + 2][arow] = a4.z;
        As[acol + 3][arow] = a4.w;
        *(float4*)&Bs[brow][bcol] = b4;
        __syncthreads();
        Aptr += 8;
        Bptr += (size_t)8 * N;

        #pragma unroll
        for (int k = 0; k < 8; k++) {
            float a[8], b[8];
            *(float4*)&a[0] = *(const float4*)&As[k][ty * 4];
            *(float4*)&a[4] = *(const float4*)&As[k][64 + ty * 4];
            *(float4*)&b[0] = *(const float4*)&Bs[k][tx * 4];
            *(float4*)&b[4] = *(const float4*)&Bs[k][64 + tx * 4];
            #pragma unroll
            for (int i = 0; i < 8; i++)
                #pragma unroll
                for (int j = 0; j < 8; j++)
                    acc[i][j] += a[i] * b[j];
        }
    }

    #pragma unroll
    for (int i = 0; i < 8; i++) {
        int lrow = (i < 4) ? (ty * 4 + i) : (64 + ty * 4 + (i - 4));
        float* Crow = C + (size_t)(bm + lrow) * N + bn;
        float4 c0 = make_float4(acc[i][0], acc[i][1], acc[i][2], acc[i][3]);
        float4 c1 = make_float4(acc[i][4], acc[i][5], acc[i][6], acc[i][7]);
        *(float4*)&Crow[tx * 4]      = c0;
        *(float4*)&Crow[64 + tx * 4] = c1;
    }
}

// ---------------------------------------------------------------------------
// Flash-attention with ALiBi bias (non-causal, |i-j| distance bias).
// One CTA = (batch b, head h, 128 query rows). 256 threads.
// Micro-tile per thread: 8(q) x 4(k) in S-GEMM, 8(q) x 4(d) in PV-GEMM.
// Q loads are warp-broadcast (16 lanes share ty) -> crossbar cost ~= K loads
// alone -> ~0.5 unique B per FMA (was 2 B/FMA with the 4x4 tile).
// smem: Qs (Q^T, 64x132), Ks (K^T, 64x68), Vs (64x68), Ps (P^T, 64x132).
// ---------------------------------------------------------------------------
#define QP 132   // q-stride for Qs/Ps (128 + 4 pad)
#define KP 68    // k/d-stride for Ks/Vs (64 + 4 pad)
#define FLASH_SMEM ((2 * 64 * QP + 2 * 64 * KP) * (int)sizeof(float))  // 102400 B

__global__ __launch_bounds__(256, 2)
void flash_alibi(const float* __restrict__ Q, const float* __restrict__ K,
                 const float* __restrict__ V, float* __restrict__ O)
{
    extern __shared__ float sm[];
    float* Qs = sm;                          // [d][q] : Qs[d*QP + q]
    float* Ks = sm + 64 * QP;                // [d][k] : Ks[d*KP + k]
    float* Vs = sm + 64 * QP + 64 * KP;      // [k][d] : Vs[k*KP + d]
    float* Ps = sm + 64 * QP + 2 * 64 * KP;  // [k][q] : Ps[k*QP + q]

    const int tid = threadIdx.x;
    const int tx  = tid & 15;       // key/dim micro-tile index (4 each -> 64)
    const int ty  = tid >> 4;       // query-row micro-tile index (8 each -> 128)
    const int bh  = blockIdx.y;
    const int b   = bh >> 4;
    const int h   = bh & 15;
    const int q0  = blockIdx.x * 128;

    // slopes[h] = (2^-0.5)^(h+1)
    const float slope = exp2f(-0.5f * (float)(h + 1));

    const float* Qb = Q + ((size_t)b * SEQ) * D_MODEL + h * HDIM;
    const float* Kb = K + ((size_t)b * SEQ) * D_MODEL + h * HDIM;
    const float* Vb = V + ((size_t)b * SEQ) * D_MODEL + h * HDIM;

    // Load Q tile (transposed) once: 128 rows x 64 d = 8192 floats, 32/thread.
    // Consecutive tid -> consecutive d (coalesced global reads).
    #pragma unroll
    for (int i = 0; i < 32; i++) {
        int idx = tid + i * 256;
        int r = idx >> 6, d = idx & 63;
        Qs[d * QP + r] = Qb[(size_t)(q0 + r) * D_MODEL + d];
    }

    float mrow[8], lrow[8], acc[8][4];
    #pragma unroll
    for (int i = 0; i < 8; i++) {
        mrow[i] = -1e30f; lrow[i] = 0.f;
        #pragma unroll
        for (int j = 0; j < 4; j++) acc[i][j] = 0.f;
    }

    for (int kt = 0; kt < SEQ; kt += 64) {
        __syncthreads();   // previous PV finished reading Ps/Vs
        #pragma unroll
        for (int i = 0; i < 16; i++) {
            int idx = tid + i * 256;
            int r = idx >> 6, d = idx & 63;
            Ks[d * KP + r] = Kb[(size_t)(kt + r) * D_MODEL + d];
            Vs[r * KP + d] = Vb[(size_t)(kt + r) * D_MODEL + d];
        }
        __syncthreads();

        // S = Q @ K^T  (8x4 per thread over d)
        float s[8][4];
        #pragma unroll
        for (int i = 0; i < 8; i++)
            #pragma unroll
            for (int j = 0; j < 4; j++) s[i][j] = 0.f;

        #pragma unroll 4
        for (int d = 0; d < 64; d++) {
            float qa[8], ka[4];
            *(float4*)&qa[0] = *(const float4*)&Qs[d * QP + ty * 8];
            *(float4*)&qa[4] = *(const float4*)&Qs[d * QP + ty * 8 + 4];
            *(float4*)&ka[0] = *(const float4*)&Ks[d * KP + tx * 4];
            #pragma unroll
            for (int i = 0; i < 8; i++)
                #pragma unroll
                for (int j = 0; j < 4; j++)
                    s[i][j] += qa[i] * ka[j];
        }

        // scale + ALiBi bias + online softmax
        // row q owned by the 16 lanes sharing ty (shfl within 16-lane half)
        #pragma unroll
        for (int i = 0; i < 8; i++) {
            float qpos = (float)(q0 + ty * 8 + i);
            #pragma unroll
            for (int j = 0; j < 4; j++) {
                float kpos = (float)(kt + tx * 4 + j);
                s[i][j] = s[i][j] * 0.125f - slope * fabsf(qpos - kpos);
            }
            float mt = fmaxf(fmaxf(s[i][0], s[i][1]), fmaxf(s[i][2], s[i][3]));
            #pragma unroll
            for (int o = 1; o < 16; o <<= 1)
                mt = fmaxf(mt, __shfl_xor_sync(0xffffffffu, mt, o));
            float mnew = fmaxf(mrow[i], mt);
            float corr = __expf(mrow[i] - mnew);   // exp(-1e30)=0 first time
            float lt = 0.f;
            #pragma unroll
            for (int j = 0; j < 4; j++) {
                float p = __expf(s[i][j] - mnew);
                s[i][j] = p;
                lt += p;
            }
            #pragma unroll
            for (int o = 1; o < 16; o <<= 1)
                lt += __shfl_xor_sync(0xffffffffu, lt, o);
            lrow[i] = lrow[i] * corr + lt;
            mrow[i] = mnew;
            #pragma unroll
            for (int j = 0; j < 4; j++) acc[i][j] *= corr;
        }

        // store P^T (separate buffer; no hazard with Ks)
        #pragma unroll
        for (int j = 0; j < 4; j++) {
            float4 p0 = make_float4(s[0][j], s[1][j], s[2][j], s[3][j]);
            float4 p1 = make_float4(s[4][j], s[5][j], s[6][j], s[7][j]);
            *(float4*)&Ps[(tx * 4 + j) * QP + ty * 8]     = p0;
            *(float4*)&Ps[(tx * 4 + j) * QP + ty * 8 + 4] = p1;
        }
        __syncthreads();

        // O += P @ V   (8x4 per thread over k)
        #pragma unroll 4
        for (int k = 0; k < 64; k++) {
            float pa[8], va[4];
            *(float4*)&pa[0] = *(const float4*)&Ps[k * QP + ty * 8];
            *(float4*)&pa[4] = *(const float4*)&Ps[k * QP + ty * 8 + 4];
            *(float4*)&va[0] = *(const float4*)&Vs[k * KP + tx * 4];
            #pragma unroll
            for (int i = 0; i < 8; i++)
                #pragma unroll
                for (int j = 0; j < 4; j++)
                    acc[i][j] += pa[i] * va[j];
        }
    }

    // normalize + store
    float* Ob = O + ((size_t)b * SEQ + q0) * D_MODEL + h * HDIM;
    #pragma unroll
    for (int i = 0; i < 8; i++) {
        float inv = 1.f / lrow[i];
        float4 o4 = make_float4(acc[i][0] * inv, acc[i][1] * inv,
                                acc[i][2] * inv, acc[i][3] * inv);
        *(float4*)&Ob[(size_t)(ty * 8 + i) * D_MODEL + tx * 4] = o4;
    }
}

// ---------------------------------------------------------------------------
// kernel_launch: Q/K/V projections -> flash attention -> output projection.
// All launches stream-ordered; graph-capturable; allocation-free.
// ---------------------------------------------------------------------------
extern "C" void kernel_launch(void* const* d_in, const int* in_sizes, int n_in,
                              void* d_out, int out_size)
{
    const float* q  = (const float*)d_in[0];
    const float* k  = (const float*)d_in[1];
    const float* v  = (const float*)d_in[2];
    const float* Wq = (const float*)d_in[3];
    const float* Wk = (const float*)d_in[4];
    const float* Wv = (const float*)d_in[5];
    const float* Wo = (const float*)d_in[6];
    float* out = (float*)d_out;

    float *pQ, *pK, *pV, *pA;
    cudaGetSymbolAddress((void**)&pQ, g_Q);
    cudaGetSymbolAddress((void**)&pK, g_K);
    cudaGetSymbolAddress((void**)&pV, g_V);
    cudaGetSymbolAddress((void**)&pA, g_A);

    cudaFuncSetAttribute(flash_alibi,
                         cudaFuncAttributeMaxDynamicSharedMemorySize,
                         FLASH_SMEM);

    dim3 gg(D_MODEL / 128, MROWS / 128);   // (8, 32)

    sgemm128<<<gg, 256>>>(q, Wq, pQ, MROWS, D_MODEL, D_MODEL);
    sgemm128<<<gg, 256>>>(k, Wk, pK, MROWS, D_MODEL, D_MODEL);
    sgemm128<<<gg, 256>>>(v, Wv, pV, MROWS, D_MODEL, D_MODEL);

    dim3 fg(SEQ / 128, BATCH * NHEADS);    // (16, 32)
    flash_alibi<<<fg, 256, FLASH_SMEM>>>(pQ, pK, pV, pA);

    sgemm128<<<gg, 256>>>(pA, Wo, out, MROWS, D_MODEL, D_MODEL);
}